// round 15
// baseline (speedup 1.0000x reference)
#include <cuda_runtime.h>
#include <cuda_fp16.h>
#include <math.h>
#include <stdint.h>

// Problem constants
#define LL 8
#define HH 12
#define CC 576
#define VV 16389
#define BB 2
#define TT 1024
#define HD 48
#define BT (BB*TT)      // 2048
#define C3 (3*CC)       // 1728
#define C2 (2*CC)       // 1152
#define CGU (2*C2)      // 2304 (gate||up)

// ---------------- scratch (device globals) ----------------------------------
__device__ float g_x   [BT*CC];
__device__ float g_x0  [BT*CC];
__device__ float g_v1  [BT*CC];
__device__ float g_vmix[BT*CC];
__device__ float g_qkv [BT*C3];
__device__ float g_gu  [BT*CGU];

// fp16 hi/lo weight mirrors (22-bit effective mantissa)
__device__ __align__(16) __half g_Wqkv_h[LL*C3*CC];
__device__ __align__(16) __half g_Wqkv_l[LL*C3*CC];
__device__ __align__(16) __half g_Wo_h  [LL*CC*CC];
__device__ __align__(16) __half g_Wo_l  [LL*CC*CC];
__device__ __align__(16) __half g_Wgu_h [LL*CGU*CC];
__device__ __align__(16) __half g_Wgu_l [LL*CGU*CC];
__device__ __align__(16) __half g_Wd_h  [LL*CC*C2];
__device__ __align__(16) __half g_Wd_l  [LL*CC*C2];
__device__ __align__(16) __half g_wte_h [VV*CC];
__device__ __align__(16) __half g_wte_l [VV*CC];
// fp16 activations
__device__ __align__(16) __half g_x0h[BT*CC];
__device__ __align__(16) __half g_hh [BT*CC];
__device__ __align__(16) __half g_yh [BT*CC];
__device__ __align__(16) __half g_gh [BT*C2];

// ---------------- helpers -----------------------------------------------------
__device__ __forceinline__ uint32_t smem_u32(const void* p) {
    return (uint32_t)__cvta_generic_to_shared(p);
}
__device__ __forceinline__ uint32_t swz(uint32_t x) { return x ^ ((x >> 3) & 0x70); }

__device__ __forceinline__ void cp16(uint32_t dst, const void* src, bool pred) {
    uint32_t sz = pred ? 16u : 0u;
    asm volatile("cp.async.cg.shared.global [%0], [%1], 16, %2;"
                 :: "r"(dst), "l"(src), "r"(sz) : "memory");
}
__device__ __forceinline__ void cp_commit() {
    asm volatile("cp.async.commit_group;" ::: "memory");
}
template<int N>
__device__ __forceinline__ void cp_wait() {
    asm volatile("cp.async.wait_group %0;" :: "n"(N) : "memory");
}
__device__ __forceinline__ void ldsm4(uint32_t* r, uint32_t a) {
    asm volatile("ldmatrix.sync.aligned.m8n8.x4.shared.b16 {%0,%1,%2,%3}, [%4];"
                 : "=r"(r[0]), "=r"(r[1]), "=r"(r[2]), "=r"(r[3]) : "r"(a));
}
__device__ __forceinline__ void mma16816(float* c, const uint32_t* a, const uint32_t* b) {
    asm volatile(
        "mma.sync.aligned.m16n8k16.row.col.f32.f16.f16.f32 "
        "{%0,%1,%2,%3}, {%4,%5,%6,%7}, {%8,%9}, {%0,%1,%2,%3};"
        : "+f"(c[0]), "+f"(c[1]), "+f"(c[2]), "+f"(c[3])
        : "r"(a[0]), "r"(a[1]), "r"(a[2]), "r"(a[3]), "r"(b[0]), "r"(b[1]));
}
// packed f32x2 FMA: acc = a*b + acc (componentwise on packed float pairs)
__device__ __forceinline__ void ffma2(unsigned long long& acc,
                                      unsigned long long a, unsigned long long b) {
    asm("fma.rn.f32x2 %0, %1, %2, %0;" : "+l"(acc) : "l"(a), "l"(b));
}

// ---------------- HMMA GEMM 128x128: C = A @ (Bh+Bl)^T -------------------------
// A fp16, B fp16 hi/lo, fp32 accum, BK=64, 2-stage cp.async, 2 CTAs/SM.
// EPI: 0 store, 1 accumulate, 2 30*tanh(v/30). M%128==0, K%64==0. N guarded.
#define STG 49152
#define GEMM_SMEM (2*STG)

template<int EPI>
__global__ void __launch_bounds__(256, 2)
hmma_gemm(const __half* __restrict__ A,
          const __half* __restrict__ Bhi, const __half* __restrict__ Blo,
          float* __restrict__ C, int M, int N, int K)
{
    extern __shared__ char smem[];
    const int tid  = threadIdx.x;
    const int lane = tid & 31;
    const int warp = tid >> 5;
    const int wm = warp & 1;
    const int wn = warp >> 1;
    const int m0 = blockIdx.y * 128, n0 = blockIdx.x * 128;
    const uint32_t sbase = smem_u32(smem);

    auto load_stage = [&](int buf, int k0) {
        const uint32_t dbase = sbase + buf * STG;
        #pragma unroll
        for (int it = 0; it < 4; it++) {
            const int u = tid + it * 256;
            const int r = u >> 3, ce = (u & 7) * 8;
            const uint32_t dsw = swz((uint32_t)(r * 128 + ce * 2));
            cp16(dbase + dsw, A + (size_t)(m0 + r) * K + k0 + ce, true);
            const bool bp = (n0 + r) < N;
            const size_t brow = (size_t)(bp ? (n0 + r) : 0) * K + k0 + ce;
            cp16(dbase + 16384 + dsw, Bhi + brow, bp);
            cp16(dbase + 32768 + dsw, Blo + brow, bp);
        }
        cp_commit();
    };

    float acc[4][4][4] = {};
    const int S = K >> 6;

    load_stage(0, 0);

    const int a_row = wm * 64 + (lane & 7) + ((lane >> 3) & 1) * 8;
    const int a_kb  = (lane >> 4) * 16;
    const int b_row = wn * 32 + (lane >> 4) * 8 + (lane & 7);
    const int b_kb  = ((lane >> 3) & 1) * 16;

    for (int s = 0; s < S; s++) {
        if (s + 1 < S) { load_stage((s + 1) & 1, (s + 1) * 64); cp_wait<1>(); }
        else           { cp_wait<0>(); }
        __syncthreads();

        const uint32_t cbase = sbase + (uint32_t)(s & 1) * STG;
        #pragma unroll
        for (int kk = 0; kk < 4; kk++) {
            uint32_t ah[4][4], bh[2][4], bl[2][4];
            #pragma unroll
            for (int i = 0; i < 4; i++) {
                uint32_t x = (uint32_t)((a_row + i * 16) * 128 + kk * 32 + a_kb);
                ldsm4(ah[i], cbase + swz(x));
            }
            #pragma unroll
            for (int jp = 0; jp < 2; jp++) {
                uint32_t x = (uint32_t)((b_row + jp * 16) * 128 + kk * 32 + b_kb);
                uint32_t bd = cbase + 16384 + swz(x);
                ldsm4(bh[jp], bd);
                ldsm4(bl[jp], bd + 16384);
            }
            #pragma unroll
            for (int i = 0; i < 4; i++)
                #pragma unroll
                for (int j = 0; j < 4; j++) {
                    mma16816(acc[i][j], ah[i], &bh[j >> 1][(j & 1) * 2]);
                    mma16816(acc[i][j], ah[i], &bl[j >> 1][(j & 1) * 2]);
                }
        }
        __syncthreads();
    }

    const int er = lane >> 2, ec = (lane & 3) * 2;
    #pragma unroll
    for (int i = 0; i < 4; i++) {
        const int m = m0 + wm * 64 + i * 16 + er;
        #pragma unroll
        for (int j = 0; j < 4; j++) {
            const int n = n0 + wn * 32 + j * 8 + ec;
            float* p0 = C + (size_t)m * N + n;
            float* p1 = C + (size_t)(m + 8) * N + n;
            #pragma unroll
            for (int q = 0; q < 2; q++) {
                if (n + q < N) {
                    float v0 = acc[i][j][q], v1 = acc[i][j][2 + q];
                    if (EPI == 1) { v0 += p0[q]; v1 += p1[q]; }
                    if (EPI == 2) {
                        v0 = 30.f * tanhf(v0 * (1.f / 30.f));
                        v1 = 30.f * tanhf(v1 * (1.f / 30.f));
                    }
                    p0[q] = v0; p1[q] = v1;
                }
            }
        }
    }
}

// ---------------- fp32 -> fp16 hi/lo conversion (weights, coalesced) -----------
__global__ void cvt_hilo(const float* __restrict__ s, __half* __restrict__ hi,
                         __half* __restrict__ lo, int n)
{
    int i = (blockIdx.x * blockDim.x + threadIdx.x) * 4;
    if (i >= n) return;
    float4 v = *(const float4*)(s + i);
    __half h0 = __float2half_rn(v.x), h1 = __float2half_rn(v.y);
    __half h2 = __float2half_rn(v.z), h3 = __float2half_rn(v.w);
    __half2 hp0, hp1, lp0, lp1;
    hp0.x = h0; hp0.y = h1; hp1.x = h2; hp1.y = h3;
    lp0.x = __float2half_rn(v.x - __half2float(h0));
    lp0.y = __float2half_rn(v.y - __half2float(h1));
    lp1.x = __float2half_rn(v.z - __half2float(h2));
    lp1.y = __float2half_rn(v.w - __half2float(h3));
    *(__half2*)(hi + i)     = hp0;
    *(__half2*)(hi + i + 2) = hp1;
    *(__half2*)(lo + i)     = lp0;
    *(__half2*)(lo + i + 2) = lp1;
}

// concat Wg||Wu rows -> combined fp16 hi/lo mirror [L][2304][576] (coalesced)
__global__ void cvt_gu(const float* __restrict__ Wg, const float* __restrict__ Wu,
                       __half* __restrict__ hi, __half* __restrict__ lo)
{
    const int total = LL * CGU * CC;
    int i = (blockIdx.x * blockDim.x + threadIdx.x) * 4;
    if (i >= total) return;
    int l = i / (CGU * CC);
    int rem = i - l * (CGU * CC);
    int r = rem / CC, c = rem - r * CC;
    const float* src = (r < C2)
        ? Wg + ((size_t)l * C2 + r) * CC + c
        : Wu + ((size_t)l * C2 + (r - C2)) * CC + c;
    float4 v = *(const float4*)src;
    __half h0 = __float2half_rn(v.x), h1 = __float2half_rn(v.y);
    __half h2 = __float2half_rn(v.z), h3 = __float2half_rn(v.w);
    __half2 hp0, hp1, lp0, lp1;
    hp0.x = h0; hp0.y = h1; hp1.x = h2; hp1.y = h3;
    lp0.x = __float2half_rn(v.x - __half2float(h0));
    lp0.y = __float2half_rn(v.y - __half2float(h1));
    lp1.x = __float2half_rn(v.z - __half2float(h2));
    lp1.y = __float2half_rn(v.w - __half2float(h3));
    *(__half2*)(hi + i)     = hp0;
    *(__half2*)(hi + i + 2) = hp1;
    *(__half2*)(lo + i)     = lp0;
    *(__half2*)(lo + i + 2) = lp1;
}

// ---------------- embedding gather ---------------------------------------------
__global__ void embed_kernel(const int* __restrict__ idx, const float* __restrict__ wte,
                             float* __restrict__ x, float* __restrict__ x0,
                             __half* __restrict__ x0h)
{
    int i = blockIdx.x * blockDim.x + threadIdx.x;
    if (i >= BT * CC) return;
    int t = i / CC, c = i - t * CC;
    float v = wte[(size_t)idx[t] * CC + c];
    x[i] = v; x0[i] = v;
    x0h[i] = __float2half_rn(v);
}

// ---------------- vmix precompute: vmix = 0.5*(V + v1) -------------------------
__global__ void vmix_kernel(const float* __restrict__ qkv, const float* __restrict__ v1,
                            float* __restrict__ vmix)
{
    int i = (blockIdx.x * blockDim.x + threadIdx.x) * 4;
    if (i >= BT * CC) return;
    int m = i / CC, c = i - m * CC;
    float4 a  = *(const float4*)(qkv + (size_t)m * C3 + 2 * CC + c);
    float4 b2 = *(const float4*)(v1 + i);
    *(float4*)(vmix + i) = make_float4(0.5f*(a.x+b2.x), 0.5f*(a.y+b2.y),
                                       0.5f*(a.z+b2.z), 0.5f*(a.w+b2.w));
}

// ---------------- fused lambda-mix + LayerNorm (fp16 out) ----------------------
__global__ void __launch_bounds__(192)
lnmix_kernel(float* __restrict__ x, const float* __restrict__ x0,
             const float* __restrict__ lam,
             const float* __restrict__ w, const float* __restrict__ b,
             __half* __restrict__ oh)
{
    const int row = blockIdx.x;
    const int tid = threadIdx.x;
    const float l0 = __ldg(lam), l1 = __ldg(lam + 1);
    float* xr = x + (size_t)row * CC;
    const float* x0r = x0 + (size_t)row * CC;
    float v0 = l0 * xr[tid]       + l1 * x0r[tid];
    float v1 = l0 * xr[tid + 192] + l1 * x0r[tid + 192];
    float v2 = l0 * xr[tid + 384] + l1 * x0r[tid + 384];
    xr[tid] = v0; xr[tid + 192] = v1; xr[tid + 384] = v2;
    __shared__ float red[6];
    float s = v0 + v1 + v2;
    #pragma unroll
    for (int off = 16; off; off >>= 1) s += __shfl_xor_sync(~0u, s, off);
    if ((tid & 31) == 0) red[tid >> 5] = s;
    __syncthreads();
    float mean = (red[0]+red[1]+red[2]+red[3]+red[4]+red[5]) * (1.f/576.f);
    float d0 = v0-mean, d1 = v1-mean, d2 = v2-mean;
    float q = d0*d0 + d1*d1 + d2*d2;
    #pragma unroll
    for (int off = 16; off; off >>= 1) q += __shfl_xor_sync(~0u, q, off);
    __syncthreads();
    if ((tid & 31) == 0) red[tid >> 5] = q;
    __syncthreads();
    float var = (red[0]+red[1]+red[2]+red[3]+red[4]+red[5]) * (1.f/576.f);
    float rstd = rsqrtf(var + 1e-5f);
    size_t base = (size_t)row * CC;
    oh[base + tid]       = __float2half_rn(d0*rstd*w[tid]       + b[tid]);
    oh[base + tid + 192] = __float2half_rn(d1*rstd*w[tid + 192] + b[tid + 192]);
    oh[base + tid + 384] = __float2half_rn(d2*rstd*w[tid + 384] + b[tid + 384]);
}

// ---------------- plain LayerNorm (fp16 out) -----------------------------------
__global__ void __launch_bounds__(192)
ln_kernel(const float* __restrict__ x, const float* __restrict__ w,
          const float* __restrict__ b, __half* __restrict__ oh)
{
    const int row = blockIdx.x;
    const int tid = threadIdx.x;
    const float* xr = x + (size_t)row * CC;
    float v0 = xr[tid], v1 = xr[tid + 192], v2 = xr[tid + 384];
    __shared__ float red[6];
    float s = v0 + v1 + v2;
    #pragma unroll
    for (int off = 16; off; off >>= 1) s += __shfl_xor_sync(~0u, s, off);
    if ((tid & 31) == 0) red[tid >> 5] = s;
    __syncthreads();
    float mean = (red[0]+red[1]+red[2]+red[3]+red[4]+red[5]) * (1.f/576.f);
    float d0 = v0-mean, d1 = v1-mean, d2 = v2-mean;
    float q = d0*d0 + d1*d1 + d2*d2;
    #pragma unroll
    for (int off = 16; off; off >>= 1) q += __shfl_xor_sync(~0u, q, off);
    __syncthreads();
    if ((tid & 31) == 0) red[tid >> 5] = q;
    __syncthreads();
    float var = (red[0]+red[1]+red[2]+red[3]+red[4]+red[5]) * (1.f/576.f);
    float rstd = rsqrtf(var + 1e-5f);
    size_t base = (size_t)row * CC;
    oh[base + tid]       = __float2half_rn(d0*rstd*w[tid]       + b[tid]);
    oh[base + tid + 192] = __float2half_rn(d1*rstd*w[tid + 192] + b[tid + 192]);
    oh[base + tid + 384] = __float2half_rn(d2*rstd*w[tid + 384] + b[tid + 384]);
}

// ---------------- fused causal attention (8 queries / block) -------------------
// Score phase uses packed fma.rn.f32x2 (2 fp32 FMAs per issue slot).
__global__ void __launch_bounds__(256)
attn_kernel(const float* __restrict__ qkv, const float* __restrict__ vmix,
            __half* __restrict__ yh)
{
    const int qb = blockIdx.x;
    const int h  = blockIdx.y;
    const int b  = blockIdx.z;
    const int tid  = threadIdx.x;
    const int lane = tid & 31;
    const int w    = tid >> 5;
    const int q0   = qb * 8;
    const int bT   = b * TT;
    const int nk   = q0 + 8;
    const float scale = 0.1443375672974065f;

    __shared__ float sc[8][TT];
    __shared__ float vt[64][HD];

    {
        const int qq = tid & 7;
        const int js = tid >> 3;
        // Q row as 12 packed float-pairs x 2 (ulonglong2 = one float4)
        ulonglong2 q2[12];
        const ulonglong2* qp =
            (const ulonglong2*)(qkv + (size_t)(bT + q0 + qq) * C3 + h * HD);
        #pragma unroll
        for (int i = 0; i < 12; i++) q2[i] = qp[i];
        for (int j = js; j < nk; j += 32) {
            const ulonglong2* kp =
                (const ulonglong2*)(qkv + (size_t)(bT + j) * C3 + CC + h * HD);
            unsigned long long acc2;
            asm("mov.b64 %0, {%1,%2};" : "=l"(acc2) : "f"(0.f), "f"(0.f));
            #pragma unroll
            for (int i = 0; i < 12; i++) {
                ulonglong2 kk = kp[i];
                ffma2(acc2, q2[i].x, kk.x);
                ffma2(acc2, q2[i].y, kk.y);
            }
            float dlo, dhi;
            asm("mov.b64 {%0,%1}, %2;" : "=f"(dlo), "=f"(dhi) : "l"(acc2));
            sc[qq][j] = (dlo + dhi) * scale;
        }
    }
    __syncthreads();

    const int jmax = q0 + w;
    float mx = -1e30f;
    for (int j = lane; j <= jmax; j += 32) mx = fmaxf(mx, sc[w][j]);
    #pragma unroll
    for (int off = 16; off; off >>= 1) mx = fmaxf(mx, __shfl_xor_sync(~0u, mx, off));
    float s = 0.f;
    for (int j = lane; j <= jmax; j += 32) {
        float e = __expf(sc[w][j] - mx);
        sc[w][j] = e;
        s += e;
    }
    #pragma unroll
    for (int off = 16; off; off >>= 1) s += __shfl_xor_sync(~0u, s, off);
    const float invZ = 1.f / s;

    float2 acc = make_float2(0.f, 0.f);
    for (int jt = 0; jt < nk; jt += 64) {
        __syncthreads();
        for (int t = tid; t < 64 * 12; t += 256) {
            const int r = t / 12, c = t % 12;
            const int j = jt + r;
            if (j < nk)
                ((float4*)vt[r])[c] =
                    ((const float4*)(vmix + (size_t)(bT + j) * CC + h * HD))[c];
        }
        __syncthreads();
        if (lane < 24) {
            const int lim = min(63, jmax - jt);
            const float* srow = sc[w] + jt;
            #pragma unroll 4
            for (int jj = 0; jj <= lim; jj++) {
                float p = srow[jj];
                float2 v = *(const float2*)&vt[jj][2 * lane];
                acc.x = fmaf(p, v.x, acc.x);
                acc.y = fmaf(p, v.y, acc.y);
            }
        }
    }
    if (lane < 24) {
        size_t yoff = (size_t)(bT + q0 + w) * CC + h * HD + 2 * lane;
        __half2 o;
        o.x = __float2half_rn(acc.x * invZ);
        o.y = __float2half_rn(acc.y * invZ);
        *(__half2*)(yh + yoff) = o;
    }
}

// ---------------- GEGLU (reads combined gate||up buffer) -----------------------
__global__ void geglu_kernel(const float* __restrict__ gu, __half* __restrict__ oh)
{
    int i = blockIdx.x * blockDim.x + threadIdx.x;
    if (i >= BT * C2) return;
    int m = i / C2, c = i - m * C2;
    float g = gu[(size_t)m * CGU + c];
    float u = gu[(size_t)m * CGU + C2 + c];
    float t = 0.7978845608028654f * (g + 0.044715f * g * g * g);
    float gl2 = 0.5f * g * (1.f + tanhf(t));
    oh[i] = __float2half_rn(gl2 * u);
}

// ---------------- host orchestration ---------------------------------------------
extern "C" void kernel_launch(void* const* d_in, const int* in_sizes, int n_in,
                              void* d_out, int out_size)
{
    const int*   idx     = (const int*)  d_in[0];
    const float* wte     = (const float*)d_in[1];
    const float* Wqkv    = (const float*)d_in[2];
    const float* Wo      = (const float*)d_in[3];
    const float* ln1w    = (const float*)d_in[4];
    const float* ln1b    = (const float*)d_in[5];
    const float* ln2w    = (const float*)d_in[6];
    const float* ln2b    = (const float*)d_in[7];
    const float* lambdas = (const float*)d_in[8];
    const float* Wg      = (const float*)d_in[9];
    const float* Wu      = (const float*)d_in[10];
    const float* Wd      = (const float*)d_in[11];
    const float* lnfw    = (const float*)d_in[12];
    const float* lnfb    = (const float*)d_in[13];
    float* out = (float*)d_out;

    float *x, *x0, *v1, *vmix, *qkv, *gu;
    cudaGetSymbolAddress((void**)&x,    g_x);
    cudaGetSymbolAddress((void**)&x0,   g_x0);
    cudaGetSymbolAddress((void**)&v1,   g_v1);
    cudaGetSymbolAddress((void**)&vmix, g_vmix);
    cudaGetSymbolAddress((void**)&qkv,  g_qkv);
    cudaGetSymbolAddress((void**)&gu,   g_gu);

    __half *Wqh,*Wql,*Woh,*Wol,*Wguh,*Wgul,*Wdh,*Wdl,*wth,*wtl;
    __half *x0h,*hh,*yh,*gh;
    cudaGetSymbolAddress((void**)&Wqh,  g_Wqkv_h); cudaGetSymbolAddress((void**)&Wql,  g_Wqkv_l);
    cudaGetSymbolAddress((void**)&Woh,  g_Wo_h);   cudaGetSymbolAddress((void**)&Wol,  g_Wo_l);
    cudaGetSymbolAddress((void**)&Wguh, g_Wgu_h);  cudaGetSymbolAddress((void**)&Wgul, g_Wgu_l);
    cudaGetSymbolAddress((void**)&Wdh,  g_Wd_h);   cudaGetSymbolAddress((void**)&Wdl,  g_Wd_l);
    cudaGetSymbolAddress((void**)&wth,  g_wte_h);  cudaGetSymbolAddress((void**)&wtl,  g_wte_l);
    cudaGetSymbolAddress((void**)&x0h,  g_x0h);
    cudaGetSymbolAddress((void**)&hh,   g_hh);
    cudaGetSymbolAddress((void**)&yh,   g_yh);
    cudaGetSymbolAddress((void**)&gh,   g_gh);

    cudaFuncSetAttribute(hmma_gemm<0>, cudaFuncAttributeMaxDynamicSharedMemorySize, GEMM_SMEM);
    cudaFuncSetAttribute(hmma_gemm<1>, cudaFuncAttributeMaxDynamicSharedMemorySize, GEMM_SMEM);
    cudaFuncSetAttribute(hmma_gemm<2>, cudaFuncAttributeMaxDynamicSharedMemorySize, GEMM_SMEM);

    // weight conversions
    {
        int n;
        n = LL*C3*CC; cvt_hilo<<<(n/4+255)/256, 256>>>(Wqkv, Wqh, Wql, n);
        n = LL*CC*CC; cvt_hilo<<<(n/4+255)/256, 256>>>(Wo,   Woh, Wol, n);
        n = LL*CC*C2; cvt_hilo<<<(n/4+255)/256, 256>>>(Wd,   Wdh, Wdl, n);
        n = VV*CC;    cvt_hilo<<<(n/4+255)/256, 256>>>(wte,  wth, wtl, n);
        n = LL*CGU*CC; cvt_gu<<<(n/4+255)/256, 256>>>(Wg, Wu, Wguh, Wgul);
    }

    const int EW  = (BT * CC + 255) / 256;
    const int EW2 = (BT * C2 + 255) / 256;
    const int VW  = (BT * CC / 4 + 255) / 256;

    embed_kernel<<<EW, 256>>>(idx, wte, x, x0, x0h);
    // v1 = x0 @ Wqkv0[v-chunk].T
    hmma_gemm<0><<<dim3((CC+127)/128, 16), 256, GEMM_SMEM>>>(
        x0h, Wqh + (size_t)C2 * CC, Wql + (size_t)C2 * CC, v1, BT, CC, CC);

    for (int l = 0; l < LL; l++) {
        const size_t oq = (size_t)l * C3 * CC;
        const size_t oo = (size_t)l * CC * CC;
        const size_t og = (size_t)l * CGU * CC;
        const size_t od = (size_t)l * CC * C2;

        lnmix_kernel<<<BT, 192>>>(x, x0, lambdas + 2*l, ln1w + l*CC, ln1b + l*CC, hh);
        hmma_gemm<0><<<dim3((C3+127)/128, 16), 256, GEMM_SMEM>>>(
            hh, Wqh + oq, Wql + oq, qkv, BT, C3, CC);
        vmix_kernel<<<VW, 256>>>(qkv, v1, vmix);
        attn_kernel<<<dim3(TT/8, HH, BB), 256>>>(qkv, vmix, yh);
        hmma_gemm<1><<<dim3((CC+127)/128, 16), 256, GEMM_SMEM>>>(
            yh, Woh + oo, Wol + oo, x, BT, CC, CC);
        ln_kernel<<<BT, 192>>>(x, ln2w + l*CC, ln2b + l*CC, hh);
        hmma_gemm<0><<<dim3(CGU/128, 16), 256, GEMM_SMEM>>>(
            hh, Wguh + og, Wgul + og, gu, BT, CGU, CC);
        geglu_kernel<<<EW2, 256>>>(gu, gh);
        hmma_gemm<1><<<dim3((CC+127)/128, 16), 256, GEMM_SMEM>>>(
            gh, Wdh + od, Wdl + od, x, BT, CC, C2);
    }

    ln_kernel<<<BT, 192>>>(x, lnfw, lnfb, hh);
    hmma_gemm<2><<<dim3((VV+127)/128, 16), 256, GEMM_SMEM>>>(
        hh, wth, wtl, out, BT, VV, CC);
}

// round 16
// speedup vs baseline: 1.0013x; 1.0013x over previous
#include <cuda_runtime.h>
#include <cuda_fp16.h>
#include <math.h>
#include <stdint.h>

// Problem constants
#define LL 8
#define HH 12
#define CC 576
#define VV 16389
#define BB 2
#define TT 1024
#define HD 48
#define BT (BB*TT)      // 2048
#define C3 (3*CC)       // 1728
#define C2 (2*CC)       // 1152
#define CGU (2*C2)      // 2304 (gate||up)

// ---------------- scratch (device globals) ----------------------------------
__device__ float g_x   [BT*CC];
__device__ float g_x0  [BT*CC];
__device__ float g_v1  [BT*CC];
__device__ float g_vmix[BT*CC];
__device__ float g_qkv [BT*C3];
__device__ float g_gu  [BT*CGU];

// fp16 hi/lo weight mirrors (22-bit effective mantissa)
__device__ __align__(16) __half g_Wqkv_h[LL*C3*CC];
__device__ __align__(16) __half g_Wqkv_l[LL*C3*CC];
__device__ __align__(16) __half g_Wo_h  [LL*CC*CC];
__device__ __align__(16) __half g_Wo_l  [LL*CC*CC];
__device__ __align__(16) __half g_Wgu_h [LL*CGU*CC];
__device__ __align__(16) __half g_Wgu_l [LL*CGU*CC];
__device__ __align__(16) __half g_Wd_h  [LL*CC*C2];
__device__ __align__(16) __half g_Wd_l  [LL*CC*C2];
__device__ __align__(16) __half g_wte_h [VV*CC];
__device__ __align__(16) __half g_wte_l [VV*CC];
// fp16 activations
__device__ __align__(16) __half g_x0h[BT*CC];
__device__ __align__(16) __half g_hh [BT*CC];
__device__ __align__(16) __half g_yh [BT*CC];
__device__ __align__(16) __half g_gh [BT*C2];

// ---------------- helpers -----------------------------------------------------
__device__ __forceinline__ uint32_t smem_u32(const void* p) {
    return (uint32_t)__cvta_generic_to_shared(p);
}
__device__ __forceinline__ uint32_t swz(uint32_t x) { return x ^ ((x >> 3) & 0x70); }

__device__ __forceinline__ void cp16(uint32_t dst, const void* src, bool pred) {
    uint32_t sz = pred ? 16u : 0u;
    asm volatile("cp.async.cg.shared.global [%0], [%1], 16, %2;"
                 :: "r"(dst), "l"(src), "r"(sz) : "memory");
}
__device__ __forceinline__ void cp_commit() {
    asm volatile("cp.async.commit_group;" ::: "memory");
}
template<int N>
__device__ __forceinline__ void cp_wait() {
    asm volatile("cp.async.wait_group %0;" :: "n"(N) : "memory");
}
__device__ __forceinline__ void ldsm4(uint32_t* r, uint32_t a) {
    asm volatile("ldmatrix.sync.aligned.m8n8.x4.shared.b16 {%0,%1,%2,%3}, [%4];"
                 : "=r"(r[0]), "=r"(r[1]), "=r"(r[2]), "=r"(r[3]) : "r"(a));
}
__device__ __forceinline__ void mma16816(float* c, const uint32_t* a, const uint32_t* b) {
    asm volatile(
        "mma.sync.aligned.m16n8k16.row.col.f32.f16.f16.f32 "
        "{%0,%1,%2,%3}, {%4,%5,%6,%7}, {%8,%9}, {%0,%1,%2,%3};"
        : "+f"(c[0]), "+f"(c[1]), "+f"(c[2]), "+f"(c[3])
        : "r"(a[0]), "r"(a[1]), "r"(a[2]), "r"(a[3]), "r"(b[0]), "r"(b[1]));
}
// packed f32x2 FMA: acc = a*b + acc (componentwise on packed float pairs)
__device__ __forceinline__ void ffma2(unsigned long long& acc,
                                      unsigned long long a, unsigned long long b) {
    asm("fma.rn.f32x2 %0, %1, %2, %0;" : "+l"(acc) : "l"(a), "l"(b));
}

// ---------------- HMMA GEMM 128x128: C = A @ (Bh+Bl)^T -------------------------
// A fp16, B fp16 hi/lo, fp32 accum, BK=64, 2-stage cp.async, 2 CTAs/SM.
// EPI: 0 store, 1 accumulate, 2 30*tanh(v/30). M%128==0, K%64==0. N guarded.
#define STG 49152
#define GEMM_SMEM (2*STG)

template<int EPI>
__global__ void __launch_bounds__(256, 2)
hmma_gemm(const __half* __restrict__ A,
          const __half* __restrict__ Bhi, const __half* __restrict__ Blo,
          float* __restrict__ C, int M, int N, int K)
{
    extern __shared__ char smem[];
    const int tid  = threadIdx.x;
    const int lane = tid & 31;
    const int warp = tid >> 5;
    const int wm = warp & 1;
    const int wn = warp >> 1;
    const int m0 = blockIdx.y * 128, n0 = blockIdx.x * 128;
    const uint32_t sbase = smem_u32(smem);

    auto load_stage = [&](int buf, int k0) {
        const uint32_t dbase = sbase + buf * STG;
        #pragma unroll
        for (int it = 0; it < 4; it++) {
            const int u = tid + it * 256;
            const int r = u >> 3, ce = (u & 7) * 8;
            const uint32_t dsw = swz((uint32_t)(r * 128 + ce * 2));
            cp16(dbase + dsw, A + (size_t)(m0 + r) * K + k0 + ce, true);
            const bool bp = (n0 + r) < N;
            const size_t brow = (size_t)(bp ? (n0 + r) : 0) * K + k0 + ce;
            cp16(dbase + 16384 + dsw, Bhi + brow, bp);
            cp16(dbase + 32768 + dsw, Blo + brow, bp);
        }
        cp_commit();
    };

    float acc[4][4][4] = {};
    const int S = K >> 6;

    load_stage(0, 0);

    const int a_row = wm * 64 + (lane & 7) + ((lane >> 3) & 1) * 8;
    const int a_kb  = (lane >> 4) * 16;
    const int b_row = wn * 32 + (lane >> 4) * 8 + (lane & 7);
    const int b_kb  = ((lane >> 3) & 1) * 16;

    for (int s = 0; s < S; s++) {
        if (s + 1 < S) { load_stage((s + 1) & 1, (s + 1) * 64); cp_wait<1>(); }
        else           { cp_wait<0>(); }
        __syncthreads();

        const uint32_t cbase = sbase + (uint32_t)(s & 1) * STG;
        #pragma unroll
        for (int kk = 0; kk < 4; kk++) {
            uint32_t ah[4][4], bh[2][4], bl[2][4];
            #pragma unroll
            for (int i = 0; i < 4; i++) {
                uint32_t x = (uint32_t)((a_row + i * 16) * 128 + kk * 32 + a_kb);
                ldsm4(ah[i], cbase + swz(x));
            }
            #pragma unroll
            for (int jp = 0; jp < 2; jp++) {
                uint32_t x = (uint32_t)((b_row + jp * 16) * 128 + kk * 32 + b_kb);
                uint32_t bd = cbase + 16384 + swz(x);
                ldsm4(bh[jp], bd);
                ldsm4(bl[jp], bd + 16384);
            }
            #pragma unroll
            for (int i = 0; i < 4; i++)
                #pragma unroll
                for (int j = 0; j < 4; j++) {
                    mma16816(acc[i][j], ah[i], &bh[j >> 1][(j & 1) * 2]);
                    mma16816(acc[i][j], ah[i], &bl[j >> 1][(j & 1) * 2]);
                }
        }
        __syncthreads();
    }

    const int er = lane >> 2, ec = (lane & 3) * 2;
    #pragma unroll
    for (int i = 0; i < 4; i++) {
        const int m = m0 + wm * 64 + i * 16 + er;
        #pragma unroll
        for (int j = 0; j < 4; j++) {
            const int n = n0 + wn * 32 + j * 8 + ec;
            float* p0 = C + (size_t)m * N + n;
            float* p1 = C + (size_t)(m + 8) * N + n;
            #pragma unroll
            for (int q = 0; q < 2; q++) {
                if (n + q < N) {
                    float v0 = acc[i][j][q], v1 = acc[i][j][2 + q];
                    if (EPI == 1) { v0 += p0[q]; v1 += p1[q]; }
                    if (EPI == 2) {
                        v0 = 30.f * tanhf(v0 * (1.f / 30.f));
                        v1 = 30.f * tanhf(v1 * (1.f / 30.f));
                    }
                    p0[q] = v0; p1[q] = v1;
                }
            }
        }
    }
}

// ---------------- fp32 -> fp16 hi/lo conversion (weights, coalesced) -----------
__global__ void cvt_hilo(const float* __restrict__ s, __half* __restrict__ hi,
                         __half* __restrict__ lo, int n)
{
    int i = (blockIdx.x * blockDim.x + threadIdx.x) * 4;
    if (i >= n) return;
    float4 v = *(const float4*)(s + i);
    __half h0 = __float2half_rn(v.x), h1 = __float2half_rn(v.y);
    __half h2 = __float2half_rn(v.z), h3 = __float2half_rn(v.w);
    __half2 hp0, hp1, lp0, lp1;
    hp0.x = h0; hp0.y = h1; hp1.x = h2; hp1.y = h3;
    lp0.x = __float2half_rn(v.x - __half2float(h0));
    lp0.y = __float2half_rn(v.y - __half2float(h1));
    lp1.x = __float2half_rn(v.z - __half2float(h2));
    lp1.y = __float2half_rn(v.w - __half2float(h3));
    *(__half2*)(hi + i)     = hp0;
    *(__half2*)(hi + i + 2) = hp1;
    *(__half2*)(lo + i)     = lp0;
    *(__half2*)(lo + i + 2) = lp1;
}

// concat Wg||Wu rows -> combined fp16 hi/lo mirror [L][2304][576] (coalesced)
__global__ void cvt_gu(const float* __restrict__ Wg, const float* __restrict__ Wu,
                       __half* __restrict__ hi, __half* __restrict__ lo)
{
    const int total = LL * CGU * CC;
    int i = (blockIdx.x * blockDim.x + threadIdx.x) * 4;
    if (i >= total) return;
    int l = i / (CGU * CC);
    int rem = i - l * (CGU * CC);
    int r = rem / CC, c = rem - r * CC;
    const float* src = (r < C2)
        ? Wg + ((size_t)l * C2 + r) * CC + c
        : Wu + ((size_t)l * C2 + (r - C2)) * CC + c;
    float4 v = *(const float4*)src;
    __half h0 = __float2half_rn(v.x), h1 = __float2half_rn(v.y);
    __half h2 = __float2half_rn(v.z), h3 = __float2half_rn(v.w);
    __half2 hp0, hp1, lp0, lp1;
    hp0.x = h0; hp0.y = h1; hp1.x = h2; hp1.y = h3;
    lp0.x = __float2half_rn(v.x - __half2float(h0));
    lp0.y = __float2half_rn(v.y - __half2float(h1));
    lp1.x = __float2half_rn(v.z - __half2float(h2));
    lp1.y = __float2half_rn(v.w - __half2float(h3));
    *(__half2*)(hi + i)     = hp0;
    *(__half2*)(hi + i + 2) = hp1;
    *(__half2*)(lo + i)     = lp0;
    *(__half2*)(lo + i + 2) = lp1;
}

// ---------------- embedding gather ---------------------------------------------
__global__ void embed_kernel(const int* __restrict__ idx, const float* __restrict__ wte,
                             float* __restrict__ x, float* __restrict__ x0,
                             __half* __restrict__ x0h)
{
    int i = blockIdx.x * blockDim.x + threadIdx.x;
    if (i >= BT * CC) return;
    int t = i / CC, c = i - t * CC;
    float v = wte[(size_t)idx[t] * CC + c];
    x[i] = v; x0[i] = v;
    x0h[i] = __float2half_rn(v);
}

// ---------------- vmix precompute: vmix = 0.5*(V + v1) -------------------------
__global__ void vmix_kernel(const float* __restrict__ qkv, const float* __restrict__ v1,
                            float* __restrict__ vmix)
{
    int i = (blockIdx.x * blockDim.x + threadIdx.x) * 4;
    if (i >= BT * CC) return;
    int m = i / CC, c = i - m * CC;
    float4 a  = *(const float4*)(qkv + (size_t)m * C3 + 2 * CC + c);
    float4 b2 = *(const float4*)(v1 + i);
    *(float4*)(vmix + i) = make_float4(0.5f*(a.x+b2.x), 0.5f*(a.y+b2.y),
                                       0.5f*(a.z+b2.z), 0.5f*(a.w+b2.w));
}

// ---------------- fused lambda-mix + LayerNorm (fp16 out) ----------------------
__global__ void __launch_bounds__(192)
lnmix_kernel(float* __restrict__ x, const float* __restrict__ x0,
             const float* __restrict__ lam,
             const float* __restrict__ w, const float* __restrict__ b,
             __half* __restrict__ oh)
{
    const int row = blockIdx.x;
    const int tid = threadIdx.x;
    const float l0 = __ldg(lam), l1 = __ldg(lam + 1);
    float* xr = x + (size_t)row * CC;
    const float* x0r = x0 + (size_t)row * CC;
    float v0 = l0 * xr[tid]       + l1 * x0r[tid];
    float v1 = l0 * xr[tid + 192] + l1 * x0r[tid + 192];
    float v2 = l0 * xr[tid + 384] + l1 * x0r[tid + 384];
    xr[tid] = v0; xr[tid + 192] = v1; xr[tid + 384] = v2;
    __shared__ float red[6];
    float s = v0 + v1 + v2;
    #pragma unroll
    for (int off = 16; off; off >>= 1) s += __shfl_xor_sync(~0u, s, off);
    if ((tid & 31) == 0) red[tid >> 5] = s;
    __syncthreads();
    float mean = (red[0]+red[1]+red[2]+red[3]+red[4]+red[5]) * (1.f/576.f);
    float d0 = v0-mean, d1 = v1-mean, d2 = v2-mean;
    float q = d0*d0 + d1*d1 + d2*d2;
    #pragma unroll
    for (int off = 16; off; off >>= 1) q += __shfl_xor_sync(~0u, q, off);
    __syncthreads();
    if ((tid & 31) == 0) red[tid >> 5] = q;
    __syncthreads();
    float var = (red[0]+red[1]+red[2]+red[3]+red[4]+red[5]) * (1.f/576.f);
    float rstd = rsqrtf(var + 1e-5f);
    size_t base = (size_t)row * CC;
    oh[base + tid]       = __float2half_rn(d0*rstd*w[tid]       + b[tid]);
    oh[base + tid + 192] = __float2half_rn(d1*rstd*w[tid + 192] + b[tid + 192]);
    oh[base + tid + 384] = __float2half_rn(d2*rstd*w[tid + 384] + b[tid + 384]);
}

// ---------------- plain LayerNorm (fp16 out) -----------------------------------
__global__ void __launch_bounds__(192)
ln_kernel(const float* __restrict__ x, const float* __restrict__ w,
          const float* __restrict__ b, __half* __restrict__ oh)
{
    const int row = blockIdx.x;
    const int tid = threadIdx.x;
    const float* xr = x + (size_t)row * CC;
    float v0 = xr[tid], v1 = xr[tid + 192], v2 = xr[tid + 384];
    __shared__ float red[6];
    float s = v0 + v1 + v2;
    #pragma unroll
    for (int off = 16; off; off >>= 1) s += __shfl_xor_sync(~0u, s, off);
    if ((tid & 31) == 0) red[tid >> 5] = s;
    __syncthreads();
    float mean = (red[0]+red[1]+red[2]+red[3]+red[4]+red[5]) * (1.f/576.f);
    float d0 = v0-mean, d1 = v1-mean, d2 = v2-mean;
    float q = d0*d0 + d1*d1 + d2*d2;
    #pragma unroll
    for (int off = 16; off; off >>= 1) q += __shfl_xor_sync(~0u, q, off);
    __syncthreads();
    if ((tid & 31) == 0) red[tid >> 5] = q;
    __syncthreads();
    float var = (red[0]+red[1]+red[2]+red[3]+red[4]+red[5]) * (1.f/576.f);
    float rstd = rsqrtf(var + 1e-5f);
    size_t base = (size_t)row * CC;
    oh[base + tid]       = __float2half_rn(d0*rstd*w[tid]       + b[tid]);
    oh[base + tid + 192] = __float2half_rn(d1*rstd*w[tid + 192] + b[tid + 192]);
    oh[base + tid + 384] = __float2half_rn(d2*rstd*w[tid + 384] + b[tid + 384]);
}

// ---------------- fused causal attention (8 queries / block) -------------------
// Score phase uses packed fma.rn.f32x2 (2 fp32 FMAs per issue slot).
__global__ void __launch_bounds__(256)
attn_kernel(const float* __restrict__ qkv, const float* __restrict__ vmix,
            __half* __restrict__ yh)
{
    const int qb = blockIdx.x;
    const int h  = blockIdx.y;
    const int b  = blockIdx.z;
    const int tid  = threadIdx.x;
    const int lane = tid & 31;
    const int w    = tid >> 5;
    const int q0   = qb * 8;
    const int bT   = b * TT;
    const int nk   = q0 + 8;
    const float scale = 0.1443375672974065f;

    __shared__ float sc[8][TT];
    __shared__ float vt[64][HD];

    {
        const int qq = tid & 7;
        const int js = tid >> 3;
        // Q row as 12 packed float-pairs x 2 (ulonglong2 = one float4)
        ulonglong2 q2[12];
        const ulonglong2* qp =
            (const ulonglong2*)(qkv + (size_t)(bT + q0 + qq) * C3 + h * HD);
        #pragma unroll
        for (int i = 0; i < 12; i++) q2[i] = qp[i];
        for (int j = js; j < nk; j += 32) {
            const ulonglong2* kp =
                (const ulonglong2*)(qkv + (size_t)(bT + j) * C3 + CC + h * HD);
            unsigned long long acc2;
            asm("mov.b64 %0, {%1,%2};" : "=l"(acc2) : "f"(0.f), "f"(0.f));
            #pragma unroll
            for (int i = 0; i < 12; i++) {
                ulonglong2 kk = kp[i];
                ffma2(acc2, q2[i].x, kk.x);
                ffma2(acc2, q2[i].y, kk.y);
            }
            float dlo, dhi;
            asm("mov.b64 {%0,%1}, %2;" : "=f"(dlo), "=f"(dhi) : "l"(acc2));
            sc[qq][j] = (dlo + dhi) * scale;
        }
    }
    __syncthreads();

    const int jmax = q0 + w;
    float mx = -1e30f;
    for (int j = lane; j <= jmax; j += 32) mx = fmaxf(mx, sc[w][j]);
    #pragma unroll
    for (int off = 16; off; off >>= 1) mx = fmaxf(mx, __shfl_xor_sync(~0u, mx, off));
    float s = 0.f;
    for (int j = lane; j <= jmax; j += 32) {
        float e = __expf(sc[w][j] - mx);
        sc[w][j] = e;
        s += e;
    }
    #pragma unroll
    for (int off = 16; off; off >>= 1) s += __shfl_xor_sync(~0u, s, off);
    const float invZ = 1.f / s;

    float2 acc = make_float2(0.f, 0.f);
    for (int jt = 0; jt < nk; jt += 64) {
        __syncthreads();
        for (int t = tid; t < 64 * 12; t += 256) {
            const int r = t / 12, c = t % 12;
            const int j = jt + r;
            if (j < nk)
                ((float4*)vt[r])[c] =
                    ((const float4*)(vmix + (size_t)(bT + j) * CC + h * HD))[c];
        }
        __syncthreads();
        if (lane < 24) {
            const int lim = min(63, jmax - jt);
            const float* srow = sc[w] + jt;
            #pragma unroll 4
            for (int jj = 0; jj <= lim; jj++) {
                float p = srow[jj];
                float2 v = *(const float2*)&vt[jj][2 * lane];
                acc.x = fmaf(p, v.x, acc.x);
                acc.y = fmaf(p, v.y, acc.y);
            }
        }
    }
    if (lane < 24) {
        size_t yoff = (size_t)(bT + q0 + w) * CC + h * HD + 2 * lane;
        __half2 o;
        o.x = __float2half_rn(acc.x * invZ);
        o.y = __float2half_rn(acc.y * invZ);
        *(__half2*)(yh + yoff) = o;
    }
}

// ---------------- GEGLU (reads combined gate||up buffer) -----------------------
__global__ void geglu_kernel(const float* __restrict__ gu, __half* __restrict__ oh)
{
    int i = blockIdx.x * blockDim.x + threadIdx.x;
    if (i >= BT * C2) return;
    int m = i / C2, c = i - m * C2;
    float g = gu[(size_t)m * CGU + c];
    float u = gu[(size_t)m * CGU + C2 + c];
    float t = 0.7978845608028654f * (g + 0.044715f * g * g * g);
    float gl2 = 0.5f * g * (1.f + tanhf(t));
    oh[i] = __float2half_rn(gl2 * u);
}

// ---------------- host orchestration ---------------------------------------------
extern "C" void kernel_launch(void* const* d_in, const int* in_sizes, int n_in,
                              void* d_out, int out_size)
{
    const int*   idx     = (const int*)  d_in[0];
    const float* wte     = (const float*)d_in[1];
    const float* Wqkv    = (const float*)d_in[2];
    const float* Wo      = (const float*)d_in[3];
    const float* ln1w    = (const float*)d_in[4];
    const float* ln1b    = (const float*)d_in[5];
    const float* ln2w    = (const float*)d_in[6];
    const float* ln2b    = (const float*)d_in[7];
    const float* lambdas = (const float*)d_in[8];
    const float* Wg      = (const float*)d_in[9];
    const float* Wu      = (const float*)d_in[10];
    const float* Wd      = (const float*)d_in[11];
    const float* lnfw    = (const float*)d_in[12];
    const float* lnfb    = (const float*)d_in[13];
    float* out = (float*)d_out;

    float *x, *x0, *v1, *vmix, *qkv, *gu;
    cudaGetSymbolAddress((void**)&x,    g_x);
    cudaGetSymbolAddress((void**)&x0,   g_x0);
    cudaGetSymbolAddress((void**)&v1,   g_v1);
    cudaGetSymbolAddress((void**)&vmix, g_vmix);
    cudaGetSymbolAddress((void**)&qkv,  g_qkv);
    cudaGetSymbolAddress((void**)&gu,   g_gu);

    __half *Wqh,*Wql,*Woh,*Wol,*Wguh,*Wgul,*Wdh,*Wdl,*wth,*wtl;
    __half *x0h,*hh,*yh,*gh;
    cudaGetSymbolAddress((void**)&Wqh,  g_Wqkv_h); cudaGetSymbolAddress((void**)&Wql,  g_Wqkv_l);
    cudaGetSymbolAddress((void**)&Woh,  g_Wo_h);   cudaGetSymbolAddress((void**)&Wol,  g_Wo_l);
    cudaGetSymbolAddress((void**)&Wguh, g_Wgu_h);  cudaGetSymbolAddress((void**)&Wgul, g_Wgu_l);
    cudaGetSymbolAddress((void**)&Wdh,  g_Wd_h);   cudaGetSymbolAddress((void**)&Wdl,  g_Wd_l);
    cudaGetSymbolAddress((void**)&wth,  g_wte_h);  cudaGetSymbolAddress((void**)&wtl,  g_wte_l);
    cudaGetSymbolAddress((void**)&x0h,  g_x0h);
    cudaGetSymbolAddress((void**)&hh,   g_hh);
    cudaGetSymbolAddress((void**)&yh,   g_yh);
    cudaGetSymbolAddress((void**)&gh,   g_gh);

    cudaFuncSetAttribute(hmma_gemm<0>, cudaFuncAttributeMaxDynamicSharedMemorySize, GEMM_SMEM);
    cudaFuncSetAttribute(hmma_gemm<1>, cudaFuncAttributeMaxDynamicSharedMemorySize, GEMM_SMEM);
    cudaFuncSetAttribute(hmma_gemm<2>, cudaFuncAttributeMaxDynamicSharedMemorySize, GEMM_SMEM);

    // weight conversions
    {
        int n;
        n = LL*C3*CC; cvt_hilo<<<(n/4+255)/256, 256>>>(Wqkv, Wqh, Wql, n);
        n = LL*CC*CC; cvt_hilo<<<(n/4+255)/256, 256>>>(Wo,   Woh, Wol, n);
        n = LL*CC*C2; cvt_hilo<<<(n/4+255)/256, 256>>>(Wd,   Wdh, Wdl, n);
        n = VV*CC;    cvt_hilo<<<(n/4+255)/256, 256>>>(wte,  wth, wtl, n);
        n = LL*CGU*CC; cvt_gu<<<(n/4+255)/256, 256>>>(Wg, Wu, Wguh, Wgul);
    }

    const int EW  = (BT * CC + 255) / 256;
    const int EW2 = (BT * C2 + 255) / 256;
    const int VW  = (BT * CC / 4 + 255) / 256;

    embed_kernel<<<EW, 256>>>(idx, wte, x, x0, x0h);
    // v1 = x0 @ Wqkv0[v-chunk].T
    hmma_gemm<0><<<dim3((CC+127)/128, 16), 256, GEMM_SMEM>>>(
        x0h, Wqh + (size_t)C2 * CC, Wql + (size_t)C2 * CC, v1, BT, CC, CC);

    for (int l = 0; l < LL; l++) {
        const size_t oq = (size_t)l * C3 * CC;
        const size_t oo = (size_t)l * CC * CC;
        const size_t og = (size_t)l * CGU * CC;
        const size_t od = (size_t)l * CC * C2;

        lnmix_kernel<<<BT, 192>>>(x, x0, lambdas + 2*l, ln1w + l*CC, ln1b + l*CC, hh);
        hmma_gemm<0><<<dim3((C3+127)/128, 16), 256, GEMM_SMEM>>>(
            hh, Wqh + oq, Wql + oq, qkv, BT, C3, CC);
        vmix_kernel<<<VW, 256>>>(qkv, v1, vmix);
        attn_kernel<<<dim3(TT/8, HH, BB), 256>>>(qkv, vmix, yh);
        hmma_gemm<1><<<dim3((CC+127)/128, 16), 256, GEMM_SMEM>>>(
            yh, Woh + oo, Wol + oo, x, BT, CC, CC);
        ln_kernel<<<BT, 192>>>(x, ln2w + l*CC, ln2b + l*CC, hh);
        hmma_gemm<0><<<dim3(CGU/128, 16), 256, GEMM_SMEM>>>(
            hh, Wguh + og, Wgul + og, gu, BT, CGU, CC);
        geglu_kernel<<<EW2, 256>>>(gu, gh);
        hmma_gemm<1><<<dim3((CC+127)/128, 16), 256, GEMM_SMEM>>>(
            gh, Wdh + od, Wdl + od, x, BT, CC, C2);
    }

    ln_kernel<<<BT, 192>>>(x, lnfw, lnfb, hh);
    hmma_gemm<2><<<dim3((VV+127)/128, 16), 256, GEMM_SMEM>>>(
        hh, wth, wtl, out, BT, VV, CC);
}

// round 17
// speedup vs baseline: 1.0332x; 1.0318x over previous
#include <cuda_runtime.h>
#include <cuda_fp16.h>
#include <math.h>
#include <stdint.h>

// Problem constants
#define LL 8
#define HH 12
#define CC 576
#define VV 16389
#define BB 2
#define TT 1024
#define HD 48
#define BT (BB*TT)      // 2048
#define C3 (3*CC)       // 1728
#define C2 (2*CC)       // 1152
#define CGU (2*C2)      // 2304 (gate||up)
#define KTP 52          // padded smem tile row stride (floats)

// ---------------- scratch (device globals) ----------------------------------
__device__ float g_x   [BT*CC];
__device__ float g_x0  [BT*CC];
__device__ float g_v1  [BT*CC];
__device__ float g_vmix[BT*CC];
__device__ float g_qkv [BT*C3];
__device__ float g_gu  [BT*CGU];

// fp16 hi/lo weight mirrors (22-bit effective mantissa)
__device__ __align__(16) __half g_Wqkv_h[LL*C3*CC];
__device__ __align__(16) __half g_Wqkv_l[LL*C3*CC];
__device__ __align__(16) __half g_Wo_h  [LL*CC*CC];
__device__ __align__(16) __half g_Wo_l  [LL*CC*CC];
__device__ __align__(16) __half g_Wgu_h [LL*CGU*CC];
__device__ __align__(16) __half g_Wgu_l [LL*CGU*CC];
__device__ __align__(16) __half g_Wd_h  [LL*CC*C2];
__device__ __align__(16) __half g_Wd_l  [LL*CC*C2];
__device__ __align__(16) __half g_wte_h [VV*CC];
__device__ __align__(16) __half g_wte_l [VV*CC];
// fp16 activations
__device__ __align__(16) __half g_x0h[BT*CC];
__device__ __align__(16) __half g_hh [BT*CC];
__device__ __align__(16) __half g_yh [BT*CC];
__device__ __align__(16) __half g_gh [BT*C2];

// ---------------- helpers -----------------------------------------------------
__device__ __forceinline__ uint32_t smem_u32(const void* p) {
    return (uint32_t)__cvta_generic_to_shared(p);
}
__device__ __forceinline__ uint32_t swz(uint32_t x) { return x ^ ((x >> 3) & 0x70); }

__device__ __forceinline__ void cp16(uint32_t dst, const void* src, bool pred) {
    uint32_t sz = pred ? 16u : 0u;
    asm volatile("cp.async.cg.shared.global [%0], [%1], 16, %2;"
                 :: "r"(dst), "l"(src), "r"(sz) : "memory");
}
__device__ __forceinline__ void cp_commit() {
    asm volatile("cp.async.commit_group;" ::: "memory");
}
template<int N>
__device__ __forceinline__ void cp_wait() {
    asm volatile("cp.async.wait_group %0;" :: "n"(N) : "memory");
}
__device__ __forceinline__ void ldsm4(uint32_t* r, uint32_t a) {
    asm volatile("ldmatrix.sync.aligned.m8n8.x4.shared.b16 {%0,%1,%2,%3}, [%4];"
                 : "=r"(r[0]), "=r"(r[1]), "=r"(r[2]), "=r"(r[3]) : "r"(a));
}
__device__ __forceinline__ void mma16816(float* c, const uint32_t* a, const uint32_t* b) {
    asm volatile(
        "mma.sync.aligned.m16n8k16.row.col.f32.f16.f16.f32 "
        "{%0,%1,%2,%3}, {%4,%5,%6,%7}, {%8,%9}, {%0,%1,%2,%3};"
        : "+f"(c[0]), "+f"(c[1]), "+f"(c[2]), "+f"(c[3])
        : "r"(a[0]), "r"(a[1]), "r"(a[2]), "r"(a[3]), "r"(b[0]), "r"(b[1]));
}

// ---------------- HMMA GEMM 128x128: C = A @ (Bh+Bl)^T -------------------------
// A fp16, B fp16 hi/lo, fp32 accum, BK=64, 2-stage cp.async, 2 CTAs/SM.
// EPI: 0 store, 1 accumulate, 2 30*tanh(v/30). M%128==0, K%64==0. N guarded.
#define STG 49152
#define GEMM_SMEM (2*STG)

template<int EPI>
__global__ void __launch_bounds__(256, 2)
hmma_gemm(const __half* __restrict__ A,
          const __half* __restrict__ Bhi, const __half* __restrict__ Blo,
          float* __restrict__ C, int M, int N, int K)
{
    extern __shared__ char smem[];
    const int tid  = threadIdx.x;
    const int lane = tid & 31;
    const int warp = tid >> 5;
    const int wm = warp & 1;
    const int wn = warp >> 1;
    const int m0 = blockIdx.y * 128, n0 = blockIdx.x * 128;
    const uint32_t sbase = smem_u32(smem);

    auto load_stage = [&](int buf, int k0) {
        const uint32_t dbase = sbase + buf * STG;
        #pragma unroll
        for (int it = 0; it < 4; it++) {
            const int u = tid + it * 256;
            const int r = u >> 3, ce = (u & 7) * 8;
            const uint32_t dsw = swz((uint32_t)(r * 128 + ce * 2));
            cp16(dbase + dsw, A + (size_t)(m0 + r) * K + k0 + ce, true);
            const bool bp = (n0 + r) < N;
            const size_t brow = (size_t)(bp ? (n0 + r) : 0) * K + k0 + ce;
            cp16(dbase + 16384 + dsw, Bhi + brow, bp);
            cp16(dbase + 32768 + dsw, Blo + brow, bp);
        }
        cp_commit();
    };

    float acc[4][4][4] = {};
    const int S = K >> 6;

    load_stage(0, 0);

    const int a_row = wm * 64 + (lane & 7) + ((lane >> 3) & 1) * 8;
    const int a_kb  = (lane >> 4) * 16;
    const int b_row = wn * 32 + (lane >> 4) * 8 + (lane & 7);
    const int b_kb  = ((lane >> 3) & 1) * 16;

    for (int s = 0; s < S; s++) {
        if (s + 1 < S) { load_stage((s + 1) & 1, (s + 1) * 64); cp_wait<1>(); }
        else           { cp_wait<0>(); }
        __syncthreads();

        const uint32_t cbase = sbase + (uint32_t)(s & 1) * STG;
        #pragma unroll
        for (int kk = 0; kk < 4; kk++) {
            uint32_t ah[4][4], bh[2][4], bl[2][4];
            #pragma unroll
            for (int i = 0; i < 4; i++) {
                uint32_t x = (uint32_t)((a_row + i * 16) * 128 + kk * 32 + a_kb);
                ldsm4(ah[i], cbase + swz(x));
            }
            #pragma unroll
            for (int jp = 0; jp < 2; jp++) {
                uint32_t x = (uint32_t)((b_row + jp * 16) * 128 + kk * 32 + b_kb);
                uint32_t bd = cbase + 16384 + swz(x);
                ldsm4(bh[jp], bd);
                ldsm4(bl[jp], bd + 16384);
            }
            #pragma unroll
            for (int i = 0; i < 4; i++)
                #pragma unroll
                for (int j = 0; j < 4; j++) {
                    mma16816(acc[i][j], ah[i], &bh[j >> 1][(j & 1) * 2]);
                    mma16816(acc[i][j], ah[i], &bl[j >> 1][(j & 1) * 2]);
                }
        }
        __syncthreads();
    }

    const int er = lane >> 2, ec = (lane & 3) * 2;
    #pragma unroll
    for (int i = 0; i < 4; i++) {
        const int m = m0 + wm * 64 + i * 16 + er;
        #pragma unroll
        for (int j = 0; j < 4; j++) {
            const int n = n0 + wn * 32 + j * 8 + ec;
            float* p0 = C + (size_t)m * N + n;
            float* p1 = C + (size_t)(m + 8) * N + n;
            #pragma unroll
            for (int q = 0; q < 2; q++) {
                if (n + q < N) {
                    float v0 = acc[i][j][q], v1 = acc[i][j][2 + q];
                    if (EPI == 1) { v0 += p0[q]; v1 += p1[q]; }
                    if (EPI == 2) {
                        v0 = 30.f * tanhf(v0 * (1.f / 30.f));
                        v1 = 30.f * tanhf(v1 * (1.f / 30.f));
                    }
                    p0[q] = v0; p1[q] = v1;
                }
            }
        }
    }
}

// ---------------- fp32 -> fp16 hi/lo conversion (weights, coalesced) -----------
__global__ void cvt_hilo(const float* __restrict__ s, __half* __restrict__ hi,
                         __half* __restrict__ lo, int n)
{
    int i = (blockIdx.x * blockDim.x + threadIdx.x) * 4;
    if (i >= n) return;
    float4 v = *(const float4*)(s + i);
    __half h0 = __float2half_rn(v.x), h1 = __float2half_rn(v.y);
    __half h2 = __float2half_rn(v.z), h3 = __float2half_rn(v.w);
    __half2 hp0, hp1, lp0, lp1;
    hp0.x = h0; hp0.y = h1; hp1.x = h2; hp1.y = h3;
    lp0.x = __float2half_rn(v.x - __half2float(h0));
    lp0.y = __float2half_rn(v.y - __half2float(h1));
    lp1.x = __float2half_rn(v.z - __half2float(h2));
    lp1.y = __float2half_rn(v.w - __half2float(h3));
    *(__half2*)(hi + i)     = hp0;
    *(__half2*)(hi + i + 2) = hp1;
    *(__half2*)(lo + i)     = lp0;
    *(__half2*)(lo + i + 2) = lp1;
}

// concat Wg||Wu rows -> combined fp16 hi/lo mirror [L][2304][576] (coalesced)
__global__ void cvt_gu(const float* __restrict__ Wg, const float* __restrict__ Wu,
                       __half* __restrict__ hi, __half* __restrict__ lo)
{
    const int total = LL * CGU * CC;
    int i = (blockIdx.x * blockDim.x + threadIdx.x) * 4;
    if (i >= total) return;
    int l = i / (CGU * CC);
    int rem = i - l * (CGU * CC);
    int r = rem / CC, c = rem - r * CC;
    const float* src = (r < C2)
        ? Wg + ((size_t)l * C2 + r) * CC + c
        : Wu + ((size_t)l * C2 + (r - C2)) * CC + c;
    float4 v = *(const float4*)src;
    __half h0 = __float2half_rn(v.x), h1 = __float2half_rn(v.y);
    __half h2 = __float2half_rn(v.z), h3 = __float2half_rn(v.w);
    __half2 hp0, hp1, lp0, lp1;
    hp0.x = h0; hp0.y = h1; hp1.x = h2; hp1.y = h3;
    lp0.x = __float2half_rn(v.x - __half2float(h0));
    lp0.y = __float2half_rn(v.y - __half2float(h1));
    lp1.x = __float2half_rn(v.z - __half2float(h2));
    lp1.y = __float2half_rn(v.w - __half2float(h3));
    *(__half2*)(hi + i)     = hp0;
    *(__half2*)(hi + i + 2) = hp1;
    *(__half2*)(lo + i)     = lp0;
    *(__half2*)(lo + i + 2) = lp1;
}

// ---------------- embedding gather ---------------------------------------------
__global__ void embed_kernel(const int* __restrict__ idx, const float* __restrict__ wte,
                             float* __restrict__ x, float* __restrict__ x0,
                             __half* __restrict__ x0h)
{
    int i = blockIdx.x * blockDim.x + threadIdx.x;
    if (i >= BT * CC) return;
    int t = i / CC, c = i - t * CC;
    float v = wte[(size_t)idx[t] * CC + c];
    x[i] = v; x0[i] = v;
    x0h[i] = __float2half_rn(v);
}

// ---------------- vmix precompute: vmix = 0.5*(V + v1) -------------------------
__global__ void vmix_kernel(const float* __restrict__ qkv, const float* __restrict__ v1,
                            float* __restrict__ vmix)
{
    int i = (blockIdx.x * blockDim.x + threadIdx.x) * 4;
    if (i >= BT * CC) return;
    int m = i / CC, c = i - m * CC;
    float4 a  = *(const float4*)(qkv + (size_t)m * C3 + 2 * CC + c);
    float4 b2 = *(const float4*)(v1 + i);
    *(float4*)(vmix + i) = make_float4(0.5f*(a.x+b2.x), 0.5f*(a.y+b2.y),
                                       0.5f*(a.z+b2.z), 0.5f*(a.w+b2.w));
}

// ---------------- fused lambda-mix + LayerNorm (fp16 out) ----------------------
__global__ void __launch_bounds__(192)
lnmix_kernel(float* __restrict__ x, const float* __restrict__ x0,
             const float* __restrict__ lam,
             const float* __restrict__ w, const float* __restrict__ b,
             __half* __restrict__ oh)
{
    const int row = blockIdx.x;
    const int tid = threadIdx.x;
    const float l0 = __ldg(lam), l1 = __ldg(lam + 1);
    float* xr = x + (size_t)row * CC;
    const float* x0r = x0 + (size_t)row * CC;
    float v0 = l0 * xr[tid]       + l1 * x0r[tid];
    float v1 = l0 * xr[tid + 192] + l1 * x0r[tid + 192];
    float v2 = l0 * xr[tid + 384] + l1 * x0r[tid + 384];
    xr[tid] = v0; xr[tid + 192] = v1; xr[tid + 384] = v2;
    __shared__ float red[6];
    float s = v0 + v1 + v2;
    #pragma unroll
    for (int off = 16; off; off >>= 1) s += __shfl_xor_sync(~0u, s, off);
    if ((tid & 31) == 0) red[tid >> 5] = s;
    __syncthreads();
    float mean = (red[0]+red[1]+red[2]+red[3]+red[4]+red[5]) * (1.f/576.f);
    float d0 = v0-mean, d1 = v1-mean, d2 = v2-mean;
    float q = d0*d0 + d1*d1 + d2*d2;
    #pragma unroll
    for (int off = 16; off; off >>= 1) q += __shfl_xor_sync(~0u, q, off);
    __syncthreads();
    if ((tid & 31) == 0) red[tid >> 5] = q;
    __syncthreads();
    float var = (red[0]+red[1]+red[2]+red[3]+red[4]+red[5]) * (1.f/576.f);
    float rstd = rsqrtf(var + 1e-5f);
    size_t base = (size_t)row * CC;
    oh[base + tid]       = __float2half_rn(d0*rstd*w[tid]       + b[tid]);
    oh[base + tid + 192] = __float2half_rn(d1*rstd*w[tid + 192] + b[tid + 192]);
    oh[base + tid + 384] = __float2half_rn(d2*rstd*w[tid + 384] + b[tid + 384]);
}

// ---------------- plain LayerNorm (fp16 out) -----------------------------------
__global__ void __launch_bounds__(192)
ln_kernel(const float* __restrict__ x, const float* __restrict__ w,
          const float* __restrict__ b, __half* __restrict__ oh)
{
    const int row = blockIdx.x;
    const int tid = threadIdx.x;
    const float* xr = x + (size_t)row * CC;
    float v0 = xr[tid], v1 = xr[tid + 192], v2 = xr[tid + 384];
    __shared__ float red[6];
    float s = v0 + v1 + v2;
    #pragma unroll
    for (int off = 16; off; off >>= 1) s += __shfl_xor_sync(~0u, s, off);
    if ((tid & 31) == 0) red[tid >> 5] = s;
    __syncthreads();
    float mean = (red[0]+red[1]+red[2]+red[3]+red[4]+red[5]) * (1.f/576.f);
    float d0 = v0-mean, d1 = v1-mean, d2 = v2-mean;
    float q = d0*d0 + d1*d1 + d2*d2;
    #pragma unroll
    for (int off = 16; off; off >>= 1) q += __shfl_xor_sync(~0u, q, off);
    __syncthreads();
    if ((tid & 31) == 0) red[tid >> 5] = q;
    __syncthreads();
    float var = (red[0]+red[1]+red[2]+red[3]+red[4]+red[5]) * (1.f/576.f);
    float rstd = rsqrtf(var + 1e-5f);
    size_t base = (size_t)row * CC;
    oh[base + tid]       = __float2half_rn(d0*rstd*w[tid]       + b[tid]);
    oh[base + tid + 192] = __float2half_rn(d1*rstd*w[tid + 192] + b[tid + 192]);
    oh[base + tid + 384] = __float2half_rn(d2*rstd*w[tid + 384] + b[tid + 384]);
}

// ---------------- fused causal attention (8 queries / block) -------------------
// Score phase stages K tiles through smem (same tile buffer reused for AV).
// Dot accumulation order identical to R11 -> bit-exact output.
__global__ void __launch_bounds__(256)
attn_kernel(const float* __restrict__ qkv, const float* __restrict__ vmix,
            __half* __restrict__ yh)
{
    const int qb = blockIdx.x;
    const int h  = blockIdx.y;
    const int b  = blockIdx.z;
    const int tid  = threadIdx.x;
    const int lane = tid & 31;
    const int w    = tid >> 5;
    const int q0   = qb * 8;
    const int bT   = b * TT;
    const int nk   = q0 + 8;
    const float scale = 0.1443375672974065f;

    __shared__ float sc[8][TT];       // 32 KB
    __shared__ float kt[64][KTP];     // 13.3 KB (K tiles, then vmix tiles)

    // ---- score phase: K staged through smem
    {
        const int qq = tid & 7;
        const int js = tid >> 3;
        float4 q4[12];
        const float4* qp = (const float4*)(qkv + (size_t)(bT + q0 + qq) * C3 + h * HD);
        #pragma unroll
        for (int i = 0; i < 12; i++) q4[i] = qp[i];

        for (int jt = 0; jt < nk; jt += 64) {
            for (int t = tid; t < 64 * 12; t += 256) {
                const int r = t / 12, c = t % 12;
                const int j = jt + r;
                if (j < nk)
                    ((float4*)kt[r])[c] =
                        ((const float4*)(qkv + (size_t)(bT + j) * C3 + CC + h * HD))[c];
            }
            __syncthreads();
            const int lim = min(64, nk - jt);
            for (int j2 = js; j2 < lim; j2 += 32) {
                const float4* kp = (const float4*)kt[j2];
                float dot = 0.f;
                #pragma unroll
                for (int i = 0; i < 12; i++) {
                    float4 kk = kp[i];
                    dot += q4[i].x*kk.x + q4[i].y*kk.y + q4[i].z*kk.z + q4[i].w*kk.w;
                }
                sc[qq][jt + j2] = dot * scale;
            }
            __syncthreads();
        }
    }

    // ---- per-warp softmax on query w
    const int jmax = q0 + w;
    float mx = -1e30f;
    for (int j = lane; j <= jmax; j += 32) mx = fmaxf(mx, sc[w][j]);
    #pragma unroll
    for (int off = 16; off; off >>= 1) mx = fmaxf(mx, __shfl_xor_sync(~0u, mx, off));
    float s = 0.f;
    for (int j = lane; j <= jmax; j += 32) {
        float e = __expf(sc[w][j] - mx);
        sc[w][j] = e;
        s += e;
    }
    #pragma unroll
    for (int off = 16; off; off >>= 1) s += __shfl_xor_sync(~0u, s, off);
    const float invZ = 1.f / s;

    // ---- AV phase: vmix tiles through the same smem buffer
    float2 acc = make_float2(0.f, 0.f);
    for (int jt = 0; jt < nk; jt += 64) {
        __syncthreads();
        for (int t = tid; t < 64 * 12; t += 256) {
            const int r = t / 12, c = t % 12;
            const int j = jt + r;
            if (j < nk)
                ((float4*)kt[r])[c] =
                    ((const float4*)(vmix + (size_t)(bT + j) * CC + h * HD))[c];
        }
        __syncthreads();
        if (lane < 24) {
            const int lim = min(63, jmax - jt);
            const float* srow = sc[w] + jt;
            #pragma unroll 4
            for (int jj = 0; jj <= lim; jj++) {
                float p = srow[jj];
                float2 v = *(const float2*)&kt[jj][2 * lane];
                acc.x = fmaf(p, v.x, acc.x);
                acc.y = fmaf(p, v.y, acc.y);
            }
        }
    }
    if (lane < 24) {
        size_t yoff = (size_t)(bT + q0 + w) * CC + h * HD + 2 * lane;
        __half2 o;
        o.x = __float2half_rn(acc.x * invZ);
        o.y = __float2half_rn(acc.y * invZ);
        *(__half2*)(yh + yoff) = o;
    }
}

// ---------------- GEGLU (reads combined gate||up buffer) -----------------------
__global__ void geglu_kernel(const float* __restrict__ gu, __half* __restrict__ oh)
{
    int i = blockIdx.x * blockDim.x + threadIdx.x;
    if (i >= BT * C2) return;
    int m = i / C2, c = i - m * C2;
    float g = gu[(size_t)m * CGU + c];
    float u = gu[(size_t)m * CGU + C2 + c];
    float t = 0.7978845608028654f * (g + 0.044715f * g * g * g);
    float gl2 = 0.5f * g * (1.f + tanhf(t));
    oh[i] = __float2half_rn(gl2 * u);
}

// ---------------- host orchestration ---------------------------------------------
extern "C" void kernel_launch(void* const* d_in, const int* in_sizes, int n_in,
                              void* d_out, int out_size)
{
    const int*   idx     = (const int*)  d_in[0];
    const float* wte     = (const float*)d_in[1];
    const float* Wqkv    = (const float*)d_in[2];
    const float* Wo      = (const float*)d_in[3];
    const float* ln1w    = (const float*)d_in[4];
    const float* ln1b    = (const float*)d_in[5];
    const float* ln2w    = (const float*)d_in[6];
    const float* ln2b    = (const float*)d_in[7];
    const float* lambdas = (const float*)d_in[8];
    const float* Wg      = (const float*)d_in[9];
    const float* Wu      = (const float*)d_in[10];
    const float* Wd      = (const float*)d_in[11];
    const float* lnfw    = (const float*)d_in[12];
    const float* lnfb    = (const float*)d_in[13];
    float* out = (float*)d_out;

    float *x, *x0, *v1, *vmix, *qkv, *gu;
    cudaGetSymbolAddress((void**)&x,    g_x);
    cudaGetSymbolAddress((void**)&x0,   g_x0);
    cudaGetSymbolAddress((void**)&v1,   g_v1);
    cudaGetSymbolAddress((void**)&vmix, g_vmix);
    cudaGetSymbolAddress((void**)&qkv,  g_qkv);
    cudaGetSymbolAddress((void**)&gu,   g_gu);

    __half *Wqh,*Wql,*Woh,*Wol,*Wguh,*Wgul,*Wdh,*Wdl,*wth,*wtl;
    __half *x0h,*hh,*yh,*gh;
    cudaGetSymbolAddress((void**)&Wqh,  g_Wqkv_h); cudaGetSymbolAddress((void**)&Wql,  g_Wqkv_l);
    cudaGetSymbolAddress((void**)&Woh,  g_Wo_h);   cudaGetSymbolAddress((void**)&Wol,  g_Wo_l);
    cudaGetSymbolAddress((void**)&Wguh, g_Wgu_h);  cudaGetSymbolAddress((void**)&Wgul, g_Wgu_l);
    cudaGetSymbolAddress((void**)&Wdh,  g_Wd_h);   cudaGetSymbolAddress((void**)&Wdl,  g_Wd_l);
    cudaGetSymbolAddress((void**)&wth,  g_wte_h);  cudaGetSymbolAddress((void**)&wtl,  g_wte_l);
    cudaGetSymbolAddress((void**)&x0h,  g_x0h);
    cudaGetSymbolAddress((void**)&hh,   g_hh);
    cudaGetSymbolAddress((void**)&yh,   g_yh);
    cudaGetSymbolAddress((void**)&gh,   g_gh);

    cudaFuncSetAttribute(hmma_gemm<0>, cudaFuncAttributeMaxDynamicSharedMemorySize, GEMM_SMEM);
    cudaFuncSetAttribute(hmma_gemm<1>, cudaFuncAttributeMaxDynamicSharedMemorySize, GEMM_SMEM);
    cudaFuncSetAttribute(hmma_gemm<2>, cudaFuncAttributeMaxDynamicSharedMemorySize, GEMM_SMEM);

    // weight conversions
    {
        int n;
        n = LL*C3*CC; cvt_hilo<<<(n/4+255)/256, 256>>>(Wqkv, Wqh, Wql, n);
        n = LL*CC*CC; cvt_hilo<<<(n/4+255)/256, 256>>>(Wo,   Woh, Wol, n);
        n = LL*CC*C2; cvt_hilo<<<(n/4+255)/256, 256>>>(Wd,   Wdh, Wdl, n);
        n = VV*CC;    cvt_hilo<<<(n/4+255)/256, 256>>>(wte,  wth, wtl, n);
        n = LL*CGU*CC; cvt_gu<<<(n/4+255)/256, 256>>>(Wg, Wu, Wguh, Wgul);
    }

    const int EW  = (BT * CC + 255) / 256;
    const int EW2 = (BT * C2 + 255) / 256;
    const int VW  = (BT * CC / 4 + 255) / 256;

    embed_kernel<<<EW, 256>>>(idx, wte, x, x0, x0h);
    // v1 = x0 @ Wqkv0[v-chunk].T
    hmma_gemm<0><<<dim3((CC+127)/128, 16), 256, GEMM_SMEM>>>(
        x0h, Wqh + (size_t)C2 * CC, Wql + (size_t)C2 * CC, v1, BT, CC, CC);

    for (int l = 0; l < LL; l++) {
        const size_t oq = (size_t)l * C3 * CC;
        const size_t oo = (size_t)l * CC * CC;
        const size_t og = (size_t)l * CGU * CC;
        const size_t od = (size_t)l * CC * C2;

        lnmix_kernel<<<BT, 192>>>(x, x0, lambdas + 2*l, ln1w + l*CC, ln1b + l*CC, hh);
        hmma_gemm<0><<<dim3((C3+127)/128, 16), 256, GEMM_SMEM>>>(
            hh, Wqh + oq, Wql + oq, qkv, BT, C3, CC);
        vmix_kernel<<<VW, 256>>>(qkv, v1, vmix);
        attn_kernel<<<dim3(TT/8, HH, BB), 256>>>(qkv, vmix, yh);
        hmma_gemm<1><<<dim3((CC+127)/128, 16), 256, GEMM_SMEM>>>(
            yh, Woh + oo, Wol + oo, x, BT, CC, CC);
        ln_kernel<<<BT, 192>>>(x, ln2w + l*CC, ln2b + l*CC, hh);
        hmma_gemm<0><<<dim3(CGU/128, 16), 256, GEMM_SMEM>>>(
            hh, Wguh + og, Wgul + og, gu, BT, CGU, CC);
        geglu_kernel<<<EW2, 256>>>(gu, gh);
        hmma_gemm<1><<<dim3((CC+127)/128, 16), 256, GEMM_SMEM>>>(
            gh, Wdh + od, Wdl + od, x, BT, CC, C2);
    }

    ln_kernel<<<BT, 192>>>(x, lnfw, lnfb, hh);
    hmma_gemm<2><<<dim3((VV+127)/128, 16), 256, GEMM_SMEM>>>(
        hh, wth, wtl, out, BT, VV, CC);
}